// round 15
// baseline (speedup 1.0000x reference)
#include <cuda_runtime.h>
#include <cstdint>

#define NSLICE 24
#define H 256
#define W 256
#define OH 512
#define OW 512

// FINAL (best measured: 41.408us bench, 36.1us ncu kernel).
// One block = 8 output rows of one (b,s) image: rows 8g..8g+7, from 6 input
// rows iy = 4g-1 .. 4g+4 (all loaded up front, MLP=6). Thread t computes
// output cols [4t,4t+3] of all 8 rows into a 16KB smem tile; the tile (which
// is CONTIGUOUS in gmem: 8 full rows) is then pushed by one
// cp.async.bulk shared->global per block (bulk async engine, no STG path).
//
// Session evidence (R0-R14): the kernel sits at the HBM write-stream wall
// (~201MB output at ~5.4TB/s write bandwidth). Falsified non-levers:
// store mechanism (STG.cs == bulk == STG.256), occupancy (42-70%, no corr),
// register diets (spill or serialize the FMA schedule), persistent blocks,
// software pipelining (breaks MLP=6 front-batching), block size 128 vs 256.
__global__ __launch_bounds__(128, 10) void convT_kernel(
    const float* __restrict__ x,
    const float* __restrict__ w,
    const float* __restrict__ bias,
    float* __restrict__ out)
{
    __shared__ alignas(128) float sbuf[8 * OW];   // 16 KB

    const int t  = threadIdx.x;        // 0..127
    const int g  = blockIdx.x;         // 0..63 -> output rows 8g..8g+7
    const int bs = blockIdx.y;         // 0..B*NSLICE-1
    const int s  = bs % NSLICE;

    // Uniform (warp-broadcast) weight loads.
    const float4 wr0 = *reinterpret_cast<const float4*>(w + s * 16 + 0);
    const float4 wr1 = *reinterpret_cast<const float4*>(w + s * 16 + 4);
    const float4 wr2 = *reinterpret_cast<const float4*>(w + s * 16 + 8);
    const float4 wr3 = *reinterpret_cast<const float4*>(w + s * 16 + 12);
    const float b0 = bias[s];

    const float* xb = x + (size_t)bs * (H * W);

    // 6 input rows j=0..5: iy = 4g - 1 + j. All loads batched up front.
    float cx[6], cy[6], L[6], R[6];
    #pragma unroll
    for (int j = 0; j < 6; ++j) {
        const int iy = 4 * g - 1 + j;
        float2 v = make_float2(0.f, 0.f);
        if (iy >= 0 && iy < H)
            v = *reinterpret_cast<const float2*>(xb + iy * W + 2 * t);
        cx[j] = v.x;
        cy[j] = v.y;
    }

    const unsigned full = 0xFFFFFFFFu;
    #pragma unroll
    for (int j = 0; j < 6; ++j) {
        L[j] = __shfl_up_sync(full, cy[j], 1);
        R[j] = __shfl_down_sync(full, cx[j], 1);
    }

    const int lane = t & 31;
    if (lane == 0) {
        #pragma unroll
        for (int j = 0; j < 6; ++j) {
            const int iy = 4 * g - 1 + j;
            L[j] = (t > 0 && iy >= 0 && iy < H) ? xb[iy * W + 2 * t - 1] : 0.f;
        }
    }
    if (lane == 31) {
        #pragma unroll
        for (int j = 0; j < 6; ++j) {
            const int iy = 4 * g - 1 + j;
            R[j] = (2 * t + 2 < W && iy >= 0 && iy < H) ? xb[iy * W + 2 * t + 2] : 0.f;
        }
    }

    const float w00 = wr0.x, w01 = wr0.y, w02 = wr0.z, w03 = wr0.w;
    const float w10 = wr1.x, w11 = wr1.y, w12 = wr1.z, w13 = wr1.w;
    const float w20 = wr2.x, w21 = wr2.y, w22 = wr2.z, w23 = wr2.w;
    const float w30 = wr3.x, w31 = wr3.y, w32 = wr3.z, w33 = wr3.w;

    float* sb = sbuf + 4 * t;

    // Even output row 2r: input rows (r-1 -> w3*), (r -> w1*)
    // Odd  output row 2r+1: input rows (r -> w2*), (r+1 -> w0*)
    // With r = 4g + k (k=0..3): r-1 -> j=k, r -> j=k+1, r+1 -> j=k+2.
#define OUT_ROW(rowidx, ja, a0_, a1_, a2_, a3_, jb, c0_, c1_, c2_, c3_)        \
    {                                                                          \
        float4 o;                                                              \
        o.x = a3_ * L[ja]  + a1_ * cx[ja] + c3_ * L[jb]  + c1_ * cx[jb] + b0;  \
        o.y = a2_ * cx[ja] + a0_ * cy[ja] + c2_ * cx[jb] + c0_ * cy[jb] + b0;  \
        o.z = a3_ * cx[ja] + a1_ * cy[ja] + c3_ * cx[jb] + c1_ * cy[jb] + b0;  \
        o.w = a2_ * cy[ja] + a0_ * R[ja]  + c2_ * cy[jb] + c0_ * R[jb]  + b0;  \
        *reinterpret_cast<float4*>(sb + (rowidx) * OW) = o;                    \
    }

    OUT_ROW(0, 0, w30, w31, w32, w33, 1, w10, w11, w12, w13);
    OUT_ROW(1, 1, w20, w21, w22, w23, 2, w00, w01, w02, w03);
    OUT_ROW(2, 1, w30, w31, w32, w33, 2, w10, w11, w12, w13);
    OUT_ROW(3, 2, w20, w21, w22, w23, 3, w00, w01, w02, w03);
    OUT_ROW(4, 2, w30, w31, w32, w33, 3, w10, w11, w12, w13);
    OUT_ROW(5, 3, w20, w21, w22, w23, 4, w00, w01, w02, w03);
    OUT_ROW(6, 3, w30, w31, w32, w33, 4, w10, w11, w12, w13);
    OUT_ROW(7, 4, w20, w21, w22, w23, 5, w00, w01, w02, w03);
#undef OUT_ROW

    // Make smem writes visible to the async (bulk-copy) proxy, then push the
    // whole contiguous 16KB tile with one bulk store.
    asm volatile("fence.proxy.async.shared::cta;" ::: "memory");
    __syncthreads();

    if (t == 0) {
        float* gdst = out + (size_t)bs * (OH * OW) + (size_t)8 * g * OW;
        uint32_t saddr;
        asm("{ .reg .u64 a; cvta.to.shared.u64 a, %1; cvt.u32.u64 %0, a; }"
            : "=r"(saddr) : "l"(sbuf));
        asm volatile(
            "cp.async.bulk.global.shared::cta.bulk_group [%0], [%1], %2;"
            :: "l"(gdst), "r"(saddr), "r"(8 * OW * 4) : "memory");
        asm volatile("cp.async.bulk.commit_group;" ::: "memory");
        // Wait only until the bulk engine has READ the smem (safe to free).
        asm volatile("cp.async.bulk.wait_group.read 0;" ::: "memory");
    }
}

extern "C" void kernel_launch(void* const* d_in, const int* in_sizes, int n_in,
                              void* d_out, int out_size) {
    const float* x = (const float*)d_in[0];
    const float* w = (const float*)d_in[1];
    const float* b = (const float*)d_in[2];
    float* out = (float*)d_out;

    const int B = in_sizes[0] / (NSLICE * H * W);   // = 8
    dim3 grid(OH / 8, B * NSLICE);                   // 64 x 192
    convT_kernel<<<grid, 128>>>(x, w, b, out);
}

// round 16
// speedup vs baseline: 1.0216x; 1.0216x over previous
#include <cuda_runtime.h>

#define NSLICE 24
#define H 256
#define W 256
#define OH 512
#define OW 512

// FINAL — statistically best variant (41.44us; STG.cs family consistently
// 41.44-41.47 across 4 independent structures vs bulk-copy family ~42.0 mean).
//
// One block = 16 output rows of one (b,s) image, as TWO independent 8-row
// tiles: rg = t>>7 selects the tile (rows 16G+8rg .. 16G+8rg+7), c = t&127
// is the col-thread (output cols 4c..4c+3). Per-tile body: 6 input rows
// front-batched (MLP=6), warp-shuffle halos with scalar-LDG fallback at warp
// edges, flat FMA schedule, 8 streaming float4 stores. No smem, no syncs.
//
// Session evidence (R0-R15): kernel sits at the HBM write-stream wall
// (201MB output at ~5.4TB/s effective write bandwidth; DRAM pipe ~65% =
// ceiling for this pattern). Falsified non-levers: store mechanism
// (STG.cs == cp.async.bulk == STG.256), occupancy 42-70% (no correlation),
// register diets (spill or serialize the FMA schedule), persistent blocks,
// software pipelining (breaks front-batched loads), smem staging.
__global__ __launch_bounds__(256, 5) void convT_kernel(
    const float* __restrict__ x,
    const float* __restrict__ w,
    const float* __restrict__ bias,
    float* __restrict__ out)
{
    const int t    = threadIdx.x;      // 0..255
    const int lane = t & 31;
    const int c    = t & 127;          // col-thread: output cols 4c..4c+3
    const int rg   = t >> 7;           // 0/1: which 8-row tile
    const int G    = blockIdx.x;       // 0..31 -> output rows 16G..16G+15
    const int bs   = blockIdx.y;       // 0..191
    const int s    = bs % NSLICE;

    const int g = 2 * G + rg;          // 8-row tile index, 0..63

    // Uniform (warp-broadcast) weight loads.
    const float4 wr0 = *reinterpret_cast<const float4*>(w + s * 16 + 0);
    const float4 wr1 = *reinterpret_cast<const float4*>(w + s * 16 + 4);
    const float4 wr2 = *reinterpret_cast<const float4*>(w + s * 16 + 8);
    const float4 wr3 = *reinterpret_cast<const float4*>(w + s * 16 + 12);
    const float b0 = bias[s];

    const float* xb = x + (size_t)bs * (H * W);

    // 6 input rows j=0..5: iy = 4g - 1 + j. All loads batched up front.
    float cx[6], cy[6], L[6], R[6];
    #pragma unroll
    for (int j = 0; j < 6; ++j) {
        const int iy = 4 * g - 1 + j;
        float2 v = make_float2(0.f, 0.f);
        if (iy >= 0 && iy < H)
            v = *reinterpret_cast<const float2*>(xb + iy * W + 2 * c);
        cx[j] = v.x;
        cy[j] = v.y;
    }

    const unsigned full = 0xFFFFFFFFu;
    #pragma unroll
    for (int j = 0; j < 6; ++j) {
        L[j] = __shfl_up_sync(full, cy[j], 1);
        R[j] = __shfl_down_sync(full, cx[j], 1);
    }

    if (lane == 0) {
        #pragma unroll
        for (int j = 0; j < 6; ++j) {
            const int iy = 4 * g - 1 + j;
            L[j] = (c > 0 && iy >= 0 && iy < H) ? xb[iy * W + 2 * c - 1] : 0.f;
        }
    }
    if (lane == 31) {
        #pragma unroll
        for (int j = 0; j < 6; ++j) {
            const int iy = 4 * g - 1 + j;
            R[j] = (2 * c + 2 < W && iy >= 0 && iy < H) ? xb[iy * W + 2 * c + 2] : 0.f;
        }
    }

    const float w00 = wr0.x, w01 = wr0.y, w02 = wr0.z, w03 = wr0.w;
    const float w10 = wr1.x, w11 = wr1.y, w12 = wr1.z, w13 = wr1.w;
    const float w20 = wr2.x, w21 = wr2.y, w22 = wr2.z, w23 = wr2.w;
    const float w30 = wr3.x, w31 = wr3.y, w32 = wr3.z, w33 = wr3.w;

    float* ob = out + (size_t)bs * (OH * OW) + (size_t)8 * g * OW + 4 * c;

    // Even output row 2r: input rows (r-1 -> w3*), (r -> w1*)
    // Odd  output row 2r+1: input rows (r -> w2*), (r+1 -> w0*)
    // With r = 4g + k (k=0..3): r-1 -> j=k, r -> j=k+1, r+1 -> j=k+2.
#define OUT_ROW(rowidx, ja, a0_, a1_, a2_, a3_, jb, c0_, c1_, c2_, c3_)        \
    {                                                                          \
        float4 o;                                                              \
        o.x = a3_ * L[ja]  + a1_ * cx[ja] + c3_ * L[jb]  + c1_ * cx[jb] + b0;  \
        o.y = a2_ * cx[ja] + a0_ * cy[ja] + c2_ * cx[jb] + c0_ * cy[jb] + b0;  \
        o.z = a3_ * cx[ja] + a1_ * cy[ja] + c3_ * cx[jb] + c1_ * cy[jb] + b0;  \
        o.w = a2_ * cy[ja] + a0_ * R[ja]  + c2_ * cy[jb] + c0_ * R[jb]  + b0;  \
        __stcs(reinterpret_cast<float4*>(ob + (size_t)(rowidx) * OW), o);      \
    }

    OUT_ROW(0, 0, w30, w31, w32, w33, 1, w10, w11, w12, w13);
    OUT_ROW(1, 1, w20, w21, w22, w23, 2, w00, w01, w02, w03);
    OUT_ROW(2, 1, w30, w31, w32, w33, 2, w10, w11, w12, w13);
    OUT_ROW(3, 2, w20, w21, w22, w23, 3, w00, w01, w02, w03);
    OUT_ROW(4, 2, w30, w31, w32, w33, 3, w10, w11, w12, w13);
    OUT_ROW(5, 3, w20, w21, w22, w23, 4, w00, w01, w02, w03);
    OUT_ROW(6, 3, w30, w31, w32, w33, 4, w10, w11, w12, w13);
    OUT_ROW(7, 4, w20, w21, w22, w23, 5, w00, w01, w02, w03);
#undef OUT_ROW
}

extern "C" void kernel_launch(void* const* d_in, const int* in_sizes, int n_in,
                              void* d_out, int out_size) {
    const float* x = (const float*)d_in[0];
    const float* w = (const float*)d_in[1];
    const float* b = (const float*)d_in[2];
    float* out = (float*)d_out;

    const int B = in_sizes[0] / (NSLICE * H * W);   // = 8
    dim3 grid(OH / 16, B * NSLICE);                  // 32 x 192 = 6144 blocks
    convT_kernel<<<grid, 256>>>(x, w, b, out);
}